// round 9
// baseline (speedup 1.0000x reference)
#include <cuda_runtime.h>

// h: [N_ROWS, DIM] fp32; S: [DIM, DIM] fp32 diagonal ±1.
// out = h @ S.T = h * diag(S) broadcast over rows — pure streaming op.
//
// R9: fat blocks (512 thr, 2048 CTAs) + DEPTH-4 pipeline + 32-bit index
// math (all element offsets < 2^23). Everything else is the proven R3/R8
// base: float4 __ldcg loads, default stores, exact shape, col-invariant
// signs. Combined streams already run at ~6.7 TB/s (~84% of HBM spec) —
// this targets the residual cross-CTA L1tex queue burst + index ALU.

template <int ITERS, int DEPTH>
__global__ __launch_bounds__(512)
void parity_scale_pipe(const float4* __restrict__ h,
                       const float* __restrict__ S,
                       float4* __restrict__ out,
                       int dim4, int dim) {
    const unsigned stride = gridDim.x * blockDim.x;        // fits 32-bit
    const unsigned idx0 = blockIdx.x * blockDim.x + threadIdx.x;

    // Column invariant: stride % dim4 == 0 guaranteed by host.
    int col4 = (int)(idx0 % (unsigned)dim4);
    int c = col4 * 4;

    float4 s;
    s.x = S[(long long)(c + 0) * dim + (c + 0)];
    s.y = S[(long long)(c + 1) * dim + (c + 1)];
    s.z = S[(long long)(c + 2) * dim + (c + 2)];
    s.w = S[(long long)(c + 3) * dim + (c + 3)];

    float4 v[DEPTH];

    #pragma unroll
    for (int i = 0; i < DEPTH; i++) {
        v[i] = __ldcg(&h[idx0 + (unsigned)i * stride]);
    }

    #pragma unroll
    for (int i = 0; i < ITERS; i++) {
        float4 r = v[i % DEPTH];
        if (i + DEPTH < ITERS) {
            v[i % DEPTH] = __ldcg(&h[idx0 + (unsigned)(i + DEPTH) * stride]);
        }
        r.x *= s.x; r.y *= s.y; r.z *= s.z; r.w *= s.w;
        out[idx0 + (unsigned)i * stride] = r;
    }
}

// ---------------- Generic fallback ------------------------------------------
__global__ void parity_scale_generic(const float4* __restrict__ h,
                                     const float* __restrict__ S,
                                     float4* __restrict__ out,
                                     long long n_vec4, int dim4, int dim) {
    long long idx0 = (long long)blockIdx.x * blockDim.x + threadIdx.x;
    long long stride = (long long)gridDim.x * blockDim.x;  // multiple of dim4

    int col4 = (int)(idx0 % (long long)dim4);
    int c = col4 * 4;

    float4 s;
    s.x = S[(long long)(c + 0) * dim + (c + 0)];
    s.y = S[(long long)(c + 1) * dim + (c + 1)];
    s.z = S[(long long)(c + 2) * dim + (c + 2)];
    s.w = S[(long long)(c + 3) * dim + (c + 3)];

    #pragma unroll 4
    for (long long idx = idx0; idx < n_vec4; idx += stride) {
        float4 v = __ldcg(&h[idx]);
        v.x *= s.x; v.y *= s.y; v.z *= s.z; v.w *= s.w;
        out[idx] = v;
    }
}

static long long gcd_ll(long long a, long long b) {
    while (b) { long long t = a % b; a = b; b = t; }
    return a;
}

extern "C" void kernel_launch(void* const* d_in, const int* in_sizes, int n_in,
                              void* d_out, int out_size) {
    const float* h = (const float*)d_in[0];
    const float* S = (const float*)d_in[1];
    float* out = (float*)d_out;

    // in_sizes[1] = DIM*DIM -> integer sqrt
    int dim = 1;
    {
        long long s = in_sizes[1];
        long long lo = 1, hi = 65536;
        while (lo < hi) {
            long long mid = (lo + hi + 1) / 2;
            if (mid * mid <= s) lo = mid; else hi = mid - 1;
        }
        dim = (int)lo;
    }

    long long total = in_sizes[0];        // N_ROWS * DIM
    long long n_vec4 = total / 4;
    int dim4 = dim / 4;

    const int threads = 512;
    const int ITERS = 8;
    long long T = n_vec4 / ITERS;
    bool exact = (n_vec4 % ITERS == 0) &&
                 (T % threads == 0) &&
                 (T % dim4 == 0) &&
                 (n_vec4 <= 0x7FFFFFFFLL) &&       // 32-bit index math valid
                 (dim % 4 == 0);

    if (exact) {
        int blocks = (int)(T / threads);
        parity_scale_pipe<ITERS, 4><<<blocks, threads>>>(
            (const float4*)h, S, (float4*)out, dim4, dim);
        return;
    }

    // Generic fallback: grid-stride multiple of dim4 (col invariance).
    const int gthreads = 256;
    long long m = (long long)dim4 / gcd_ll(gthreads, dim4);
    long long want = 148LL * 32;
    long long blocks = ((want + m - 1) / m) * m;
    long long cover = (n_vec4 + gthreads - 1) / gthreads;
    long long cover_r = ((cover + m - 1) / m) * m;
    if (blocks > cover_r) blocks = cover_r;
    if (blocks < m) blocks = m;

    parity_scale_generic<<<(int)blocks, gthreads>>>(
        (const float4*)h, S, (float4*)out, n_vec4, dim4, dim);
}

// round 10
// speedup vs baseline: 1.0056x; 1.0056x over previous
#include <cuda_runtime.h>

// h: [N_ROWS, DIM] fp32; S: [DIM, DIM] fp32 diagonal ±1.
// out = h @ S.T = h * diag(S) broadcast over rows — pure streaming op.
//
// FINAL (R3 config): this problem is bound by B300's LTS throughput cap
// (~6300 B/cyc, path-independent): 268 MB of mandatory L2 traffic / 6.7 TB/s
// = ~40us kernel floor, which all structural variants (MLP 4/8, pipelined,
// fat blocks, v8 loads, stcs/evict_last/cache_hint policies) hit or miss
// downward. Best measured: float4 __ldcg, MLP=8 front-batch, 4096x256,
// exact-shape tiling, default stores.

template <int ITERS>
__global__ __launch_bounds__(256)
void parity_scale_exact(const float4* __restrict__ h,
                        const float* __restrict__ S,
                        float4* __restrict__ out,
                        int dim4, int dim) {
    const long long stride = (long long)gridDim.x * blockDim.x;
    const long long idx0 = (long long)blockIdx.x * blockDim.x + threadIdx.x;

    // Column invariant: stride % dim4 == 0 guaranteed by host.
    int col4 = (int)(idx0 % (long long)dim4);
    int c = col4 * 4;

    float4 s;
    s.x = S[(long long)(c + 0) * dim + (c + 0)];
    s.y = S[(long long)(c + 1) * dim + (c + 1)];
    s.z = S[(long long)(c + 2) * dim + (c + 2)];
    s.w = S[(long long)(c + 3) * dim + (c + 3)];

    // Front-batch all loads: MLP = ITERS per thread.
    float4 v[ITERS];
    #pragma unroll
    for (int i = 0; i < ITERS; i++) {
        v[i] = __ldcg(&h[idx0 + (long long)i * stride]);
    }
    #pragma unroll
    for (int i = 0; i < ITERS; i++) {
        float4 r = v[i];
        r.x *= s.x; r.y *= s.y; r.z *= s.z; r.w *= s.w;
        out[idx0 + (long long)i * stride] = r;
    }
}

// ---------------- Generic fallback ------------------------------------------
__global__ void parity_scale_generic(const float4* __restrict__ h,
                                     const float* __restrict__ S,
                                     float4* __restrict__ out,
                                     long long n_vec4, int dim4, int dim) {
    long long idx0 = (long long)blockIdx.x * blockDim.x + threadIdx.x;
    long long stride = (long long)gridDim.x * blockDim.x;  // multiple of dim4

    int col4 = (int)(idx0 % (long long)dim4);
    int c = col4 * 4;

    float4 s;
    s.x = S[(long long)(c + 0) * dim + (c + 0)];
    s.y = S[(long long)(c + 1) * dim + (c + 1)];
    s.z = S[(long long)(c + 2) * dim + (c + 2)];
    s.w = S[(long long)(c + 3) * dim + (c + 3)];

    #pragma unroll 4
    for (long long idx = idx0; idx < n_vec4; idx += stride) {
        float4 v = __ldcg(&h[idx]);
        v.x *= s.x; v.y *= s.y; v.z *= s.z; v.w *= s.w;
        out[idx] = v;
    }
}

static long long gcd_ll(long long a, long long b) {
    while (b) { long long t = a % b; a = b; b = t; }
    return a;
}

extern "C" void kernel_launch(void* const* d_in, const int* in_sizes, int n_in,
                              void* d_out, int out_size) {
    const float* h = (const float*)d_in[0];
    const float* S = (const float*)d_in[1];
    float* out = (float*)d_out;

    // in_sizes[1] = DIM*DIM -> integer sqrt
    int dim = 1;
    {
        long long s = in_sizes[1];
        long long lo = 1, hi = 65536;
        while (lo < hi) {
            long long mid = (lo + hi + 1) / 2;
            if (mid * mid <= s) lo = mid; else hi = mid - 1;
        }
        dim = (int)lo;
    }

    long long total = in_sizes[0];        // N_ROWS * DIM
    long long n_vec4 = total / 4;
    int dim4 = dim / 4;

    const int threads = 256;

    const int ITERS = 8;
    long long T = n_vec4 / ITERS;
    bool exact = (n_vec4 % ITERS == 0) &&
                 (T % threads == 0) &&
                 (T % dim4 == 0) &&
                 (T / threads <= 2147483647LL) &&
                 (dim % 4 == 0);

    if (exact) {
        int blocks = (int)(T / threads);
        parity_scale_exact<ITERS><<<blocks, threads>>>(
            (const float4*)h, S, (float4*)out, dim4, dim);
        return;
    }

    // Generic fallback: grid-stride multiple of dim4 (col invariance).
    long long m = (long long)dim4 / gcd_ll(threads, dim4);
    long long want = 148LL * 32;
    long long blocks = ((want + m - 1) / m) * m;
    long long cover = (n_vec4 + threads - 1) / threads;
    long long cover_r = ((cover + m - 1) / m) * m;
    if (blocks > cover_r) blocks = cover_r;
    if (blocks < m) blocks = m;

    parity_scale_generic<<<(int)blocks, threads>>>(
        (const float4*)h, S, (float4*)out, n_vec4, dim4, dim);
}